// round 3
// baseline (speedup 1.0000x reference)
#include <cuda_runtime.h>
#include <cuda_bf16.h>
#include <stdint.h>

#ifndef CLAMP_VAL
#define CLAMP_VAL 10000.0f
#endif

__device__ __forceinline__ float clampv(float v) {
    return fminf(fmaxf(v, -CLAMP_VAL), CLAMP_VAL);
}

// ---------------------------------------------------------------------------
// Fast path: in_w = 8192, out_w = 8191. One block per row.
// Both loads and stores are aligned 128-bit. The per-row 4-byte phase
// (lead = row & 3) is resolved with a register shuffle from two overlapping
// aligned input vectors; the second load stream is a guaranteed L1/L2 hit.
// Head (lead scalars) and tail (<=4 scalars incl. averaged col 8190) are
// handled separately so the vector loop never touches col 8190.
// ---------------------------------------------------------------------------
__global__ void __launch_bounds__(256)
binagg_row_kernel(const float4* __restrict__ x4, float* __restrict__ out)
{
    const unsigned r = blockIdx.x;
    const float4* xrow = x4 + (size_t)r * 2048u;           // 8192 floats / 4
    const float*  xs   = (const float*)xrow;
    float*        orow = out + (size_t)r * 8191u;
    const int tid  = threadIdx.x;
    const int lead = (int)(r & 3u);                         // out-row phase

    // Head: cols 0..lead-1 (0..3 scalars)
    if (tid < lead) orow[tid] = clampv(__ldg(xs + tid));

    // Aligned out-vectors covering cols [lead, lead+4*count) with max col <= 8189
    const int count = ((8186 - lead) >> 2) + 1;             // 2047 or 2046
    float4* ov = (float4*)(orow + lead);                    // 16B aligned by construction

    if (lead == 0) {
        #pragma unroll 4
        for (int v = tid; v < count; v += 256) {
            float4 a = __ldcs(&xrow[v]);
            float4 s = { clampv(a.x), clampv(a.y), clampv(a.z), clampv(a.w) };
            __stcs(&ov[v], s);
        }
    } else if (lead == 1) {
        #pragma unroll 4
        for (int v = tid; v < count; v += 256) {
            float4 a = __ldcs(&xrow[v]);
            float4 b = __ldcs(&xrow[v + 1]);
            float4 s = { clampv(a.y), clampv(a.z), clampv(a.w), clampv(b.x) };
            __stcs(&ov[v], s);
        }
    } else if (lead == 2) {
        #pragma unroll 4
        for (int v = tid; v < count; v += 256) {
            float4 a = __ldcs(&xrow[v]);
            float4 b = __ldcs(&xrow[v + 1]);
            float4 s = { clampv(a.z), clampv(a.w), clampv(b.x), clampv(b.y) };
            __stcs(&ov[v], s);
        }
    } else {
        #pragma unroll 4
        for (int v = tid; v < count; v += 256) {
            float4 a = __ldcs(&xrow[v]);
            float4 b = __ldcs(&xrow[v + 1]);
            float4 s = { clampv(a.w), clampv(b.x), clampv(b.y), clampv(b.z) };
            __stcs(&ov[v], s);
        }
    }

    // Tail: cols [lead + 4*count, 8190], 1..4 scalars; col 8190 = mean of last two inputs
    const int tstart = lead + 4 * count;
    for (int c = tstart + tid; c <= 8190; c += 256) {
        float val = (c == 8190)
                  ? 0.5f * (__ldg(xs + 8190) + __ldg(xs + 8191))
                  : __ldg(xs + c);
        orow[c] = clampv(val);
    }
}

// ---------------------------------------------------------------------------
// Generic fallback (any in_w/out_w): flat output indexing, scalar.
// ---------------------------------------------------------------------------
__global__ void __launch_bounds__(256)
binagg_generic_kernel(const float* __restrict__ x, float* __restrict__ out,
                      int in_w, int out_w, unsigned total)
{
    unsigned oo = blockIdx.x * blockDim.x + threadIdx.x;
    if (oo >= total) return;
    unsigned r = oo / (unsigned)out_w;
    unsigned c = oo - r * (unsigned)out_w;
    const float* xr = x + (size_t)r * (size_t)in_w;
    float val;
    if (c < (unsigned)(out_w - 1)) {
        val = __ldg(xr + c);
    } else {
        float s = 0.0f;
        for (int k = out_w - 1; k < in_w; ++k) s += __ldg(xr + k);
        val = s / (float)(in_w - out_w + 1);
    }
    out[oo] = clampv(val);
}

extern "C" void kernel_launch(void* const* d_in, const int* in_sizes, int n_in,
                              void* d_out, int out_size)
{
    const float* x = (const float*)d_in[0];
    float* out = (float*)d_out;

    const int in_w = 8192;
    int batch = in_sizes[0] / in_w;
    int out_w = (batch > 0) ? out_size / batch : 0;

    bool fast = (batch > 0) &&
                (batch * in_w == in_sizes[0]) &&
                (out_w == in_w - 1) &&
                ((size_t)batch * (size_t)out_w == (size_t)out_size);

    if (fast) {
        binagg_row_kernel<<<batch, 256>>>((const float4*)x, out);
    } else {
        int iw = in_sizes[0];
        int ow = out_size;
        for (int cand = 8192; cand >= 1; cand >>= 1) {
            if (in_sizes[0] % cand == 0) {
                int bb = in_sizes[0] / cand;
                if (bb > 0 && out_size % bb == 0) { iw = cand; ow = out_size / bb; break; }
            }
        }
        unsigned total = (unsigned)out_size;
        unsigned blocks = (total + 255) / 256;
        binagg_generic_kernel<<<blocks, 256>>>(x, out, iw, ow, total);
    }
}

// round 4
// speedup vs baseline: 1.0576x; 1.0576x over previous
#include <cuda_runtime.h>
#include <cuda_bf16.h>
#include <stdint.h>

#ifndef CLAMP_VAL
#define CLAMP_VAL 10000.0f
#endif

__device__ __forceinline__ float clampv(float v) {
    return fminf(fmaxf(v, -CLAMP_VAL), CLAMP_VAL);
}

// ---------------------------------------------------------------------------
// Fast path: in_w = 8192, out_w = 8191. One block per row.
// Aligned 128-bit on BOTH sides. Per-row 4-byte phase (lead = row & 3)
// resolved by register shuffle from two overlapping aligned input vectors.
// Loads use default caching (__ldg) so the overlapping line is an L1 hit —
// NOT __ldcs (R3's evict-first hint caused DRAM refetch of overlapped lines).
// Stores use __stcs (zero-reuse write stream, evict-first).
// ---------------------------------------------------------------------------
__global__ void __launch_bounds__(256)
binagg_row_kernel(const float4* __restrict__ x4, float* __restrict__ out)
{
    const unsigned r = blockIdx.x;
    const float4* xrow = x4 + (size_t)r * 2048u;           // 8192 floats / 4
    const float*  xs   = (const float*)xrow;
    float*        orow = out + (size_t)r * 8191u;
    const int tid  = threadIdx.x;
    const int lead = (int)(r & 3u);                         // out-row phase

    // Head: cols 0..lead-1 (0..3 scalars)
    if (tid < lead) orow[tid] = clampv(__ldg(xs + tid));

    // Aligned out-vectors covering cols [lead, lead+4*count), max col <= 8189
    const int count = ((8186 - lead) >> 2) + 1;             // 2047 or 2046
    float4* ov = (float4*)(orow + lead);                    // 16B aligned

    if (lead == 0) {
        #pragma unroll 4
        for (int v = tid; v < count; v += 256) {
            float4 a = __ldg(&xrow[v]);
            float4 s = { clampv(a.x), clampv(a.y), clampv(a.z), clampv(a.w) };
            __stcs(&ov[v], s);
        }
    } else if (lead == 1) {
        #pragma unroll 4
        for (int v = tid; v < count; v += 256) {
            float4 a = __ldg(&xrow[v]);
            float4 b = __ldg(&xrow[v + 1]);
            float4 s = { clampv(a.y), clampv(a.z), clampv(a.w), clampv(b.x) };
            __stcs(&ov[v], s);
        }
    } else if (lead == 2) {
        #pragma unroll 4
        for (int v = tid; v < count; v += 256) {
            float4 a = __ldg(&xrow[v]);
            float4 b = __ldg(&xrow[v + 1]);
            float4 s = { clampv(a.z), clampv(a.w), clampv(b.x), clampv(b.y) };
            __stcs(&ov[v], s);
        }
    } else {
        #pragma unroll 4
        for (int v = tid; v < count; v += 256) {
            float4 a = __ldg(&xrow[v]);
            float4 b = __ldg(&xrow[v + 1]);
            float4 s = { clampv(a.w), clampv(b.x), clampv(b.y), clampv(b.z) };
            __stcs(&ov[v], s);
        }
    }

    // Tail: cols [lead + 4*count, 8190]; col 8190 = mean of last two inputs
    const int tstart = lead + 4 * count;
    for (int c = tstart + tid; c <= 8190; c += 256) {
        float val = (c == 8190)
                  ? 0.5f * (__ldg(xs + 8190) + __ldg(xs + 8191))
                  : __ldg(xs + c);
        orow[c] = clampv(val);
    }
}

// ---------------------------------------------------------------------------
// Generic fallback (any in_w/out_w): flat output indexing, scalar.
// ---------------------------------------------------------------------------
__global__ void __launch_bounds__(256)
binagg_generic_kernel(const float* __restrict__ x, float* __restrict__ out,
                      int in_w, int out_w, unsigned total)
{
    unsigned oo = blockIdx.x * blockDim.x + threadIdx.x;
    if (oo >= total) return;
    unsigned r = oo / (unsigned)out_w;
    unsigned c = oo - r * (unsigned)out_w;
    const float* xr = x + (size_t)r * (size_t)in_w;
    float val;
    if (c < (unsigned)(out_w - 1)) {
        val = __ldg(xr + c);
    } else {
        float s = 0.0f;
        for (int k = out_w - 1; k < in_w; ++k) s += __ldg(xr + k);
        val = s / (float)(in_w - out_w + 1);
    }
    out[oo] = clampv(val);
}

extern "C" void kernel_launch(void* const* d_in, const int* in_sizes, int n_in,
                              void* d_out, int out_size)
{
    const float* x = (const float*)d_in[0];
    float* out = (float*)d_out;

    const int in_w = 8192;
    int batch = in_sizes[0] / in_w;
    int out_w = (batch > 0) ? out_size / batch : 0;

    bool fast = (batch > 0) &&
                (batch * in_w == in_sizes[0]) &&
                (out_w == in_w - 1) &&
                ((size_t)batch * (size_t)out_w == (size_t)out_size);

    if (fast) {
        binagg_row_kernel<<<batch, 256>>>((const float4*)x, out);
    } else {
        int iw = in_sizes[0];
        int ow = out_size;
        for (int cand = 8192; cand >= 1; cand >>= 1) {
            if (in_sizes[0] % cand == 0) {
                int bb = in_sizes[0] / cand;
                if (bb > 0 && out_size % bb == 0) { iw = cand; ow = out_size / bb; break; }
            }
        }
        unsigned total = (unsigned)out_size;
        unsigned blocks = (total + 255) / 256;
        binagg_generic_kernel<<<blocks, 256>>>(x, out, iw, ow, total);
    }
}

// round 5
// speedup vs baseline: 1.0583x; 1.0007x over previous
#include <cuda_runtime.h>
#include <cuda_bf16.h>
#include <stdint.h>

#ifndef CLAMP_VAL
#define CLAMP_VAL 10000.0f
#endif

__device__ __forceinline__ float clampv(float v) {
    return fminf(fmaxf(v, -CLAMP_VAL), CLAMP_VAL);
}

// ---------------------------------------------------------------------------
// Fast path: in_w = 8192, out_w = 8191. ROWS_PER_BLOCK rows per block.
// Aligned 128-bit on BOTH sides; per-row 4-byte phase (lead = row & 3)
// resolved by register shuffle from two overlapping aligned input vectors
// (default-cached loads: the overlap line is an L1 hit). Loads for 4
// iterations are front-batched before any store to maximize per-warp MLP.
// ---------------------------------------------------------------------------
template<int LEAD>
__device__ __forceinline__ float4 shuf(const float4& a, const float4& b)
{
    float4 s;
    if (LEAD == 0)      { s.x = a.x; s.y = a.y; s.z = a.z; s.w = a.w; }
    else if (LEAD == 1) { s.x = a.y; s.y = a.z; s.z = a.w; s.w = b.x; }
    else if (LEAD == 2) { s.x = a.z; s.y = a.w; s.z = b.x; s.w = b.y; }
    else                { s.x = a.w; s.y = b.x; s.z = b.y; s.w = b.z; }
    s.x = clampv(s.x); s.y = clampv(s.y); s.z = clampv(s.z); s.w = clampv(s.w);
    return s;
}

template<int LEAD, int TPB>
__device__ __forceinline__ void row_body(const float4* __restrict__ xrow,
                                         float4* __restrict__ ov,
                                         int count, int tid)
{
    int v = tid;
    // Main: 4 front-batched iterations (8 outstanding LDG.128 per thread)
    for (; v + 3 * TPB < count; v += 4 * TPB) {
        float4 a0 = __ldg(&xrow[v]);
        float4 a1 = __ldg(&xrow[v + TPB]);
        float4 a2 = __ldg(&xrow[v + 2 * TPB]);
        float4 a3 = __ldg(&xrow[v + 3 * TPB]);
        float4 b0, b1, b2, b3;
        if (LEAD != 0) {
            b0 = __ldg(&xrow[v + 1]);
            b1 = __ldg(&xrow[v + TPB + 1]);
            b2 = __ldg(&xrow[v + 2 * TPB + 1]);
            b3 = __ldg(&xrow[v + 3 * TPB + 1]);
        }
        __stcs(&ov[v],           shuf<LEAD>(a0, b0));
        __stcs(&ov[v + TPB],     shuf<LEAD>(a1, b1));
        __stcs(&ov[v + 2 * TPB], shuf<LEAD>(a2, b2));
        __stcs(&ov[v + 3 * TPB], shuf<LEAD>(a3, b3));
    }
    for (; v < count; v += TPB) {
        float4 a = __ldg(&xrow[v]);
        float4 b;
        if (LEAD != 0) b = __ldg(&xrow[v + 1]);
        __stcs(&ov[v], shuf<LEAD>(a, b));
    }
}

constexpr int TPB = 256;
constexpr int ROWS_PER_BLOCK = 2;

__global__ void __launch_bounds__(TPB)
binagg_row_kernel(const float4* __restrict__ x4, float* __restrict__ out,
                  unsigned batch)
{
    for (int rr = 0; rr < ROWS_PER_BLOCK; ++rr) {
        const unsigned r = blockIdx.x * ROWS_PER_BLOCK + rr;
        if (r >= batch) return;
        const float4* xrow = x4 + (size_t)r * 2048u;
        const float*  xs   = (const float*)xrow;
        float*        orow = out + (size_t)r * 8191u;
        const int tid  = threadIdx.x;
        const int lead = (int)(r & 3u);

        // Head: cols 0..lead-1
        if (tid < lead) orow[tid] = clampv(__ldg(xs + tid));

        const int count = ((8186 - lead) >> 2) + 1;       // 2047 or 2046
        float4* ov = (float4*)(orow + lead);              // 16B aligned

        switch (lead) {
            case 0: row_body<0, TPB>(xrow, ov, count, tid); break;
            case 1: row_body<1, TPB>(xrow, ov, count, tid); break;
            case 2: row_body<2, TPB>(xrow, ov, count, tid); break;
            default: row_body<3, TPB>(xrow, ov, count, tid); break;
        }

        // Tail: cols [lead + 4*count, 8190]; col 8190 = mean of last two inputs
        const int tstart = lead + 4 * count;
        for (int c = tstart + tid; c <= 8190; c += TPB) {
            float val = (c == 8190)
                      ? 0.5f * (__ldg(xs + 8190) + __ldg(xs + 8191))
                      : __ldg(xs + c);
            orow[c] = clampv(val);
        }
    }
}

// ---------------------------------------------------------------------------
// Generic fallback (any in_w/out_w): flat output indexing, scalar.
// ---------------------------------------------------------------------------
__global__ void __launch_bounds__(256)
binagg_generic_kernel(const float* __restrict__ x, float* __restrict__ out,
                      int in_w, int out_w, unsigned total)
{
    unsigned oo = blockIdx.x * blockDim.x + threadIdx.x;
    if (oo >= total) return;
    unsigned r = oo / (unsigned)out_w;
    unsigned c = oo - r * (unsigned)out_w;
    const float* xr = x + (size_t)r * (size_t)in_w;
    float val;
    if (c < (unsigned)(out_w - 1)) {
        val = __ldg(xr + c);
    } else {
        float s = 0.0f;
        for (int k = out_w - 1; k < in_w; ++k) s += __ldg(xr + k);
        val = s / (float)(in_w - out_w + 1);
    }
    out[oo] = clampv(val);
}

extern "C" void kernel_launch(void* const* d_in, const int* in_sizes, int n_in,
                              void* d_out, int out_size)
{
    const float* x = (const float*)d_in[0];
    float* out = (float*)d_out;

    const int in_w = 8192;
    int batch = in_sizes[0] / in_w;
    int out_w = (batch > 0) ? out_size / batch : 0;

    bool fast = (batch > 0) &&
                (batch * in_w == in_sizes[0]) &&
                (out_w == in_w - 1) &&
                ((size_t)batch * (size_t)out_w == (size_t)out_size);

    if (fast) {
        unsigned blocks = (unsigned)((batch + ROWS_PER_BLOCK - 1) / ROWS_PER_BLOCK);
        binagg_row_kernel<<<blocks, TPB>>>((const float4*)x, out, (unsigned)batch);
    } else {
        int iw = in_sizes[0];
        int ow = out_size;
        for (int cand = 8192; cand >= 1; cand >>= 1) {
            if (in_sizes[0] % cand == 0) {
                int bb = in_sizes[0] / cand;
                if (bb > 0 && out_size % bb == 0) { iw = cand; ow = out_size / bb; break; }
            }
        }
        unsigned total = (unsigned)out_size;
        unsigned blocks = (total + 255) / 256;
        binagg_generic_kernel<<<blocks, 256>>>(x, out, iw, ow, total);
    }
}

// round 6
// speedup vs baseline: 1.0955x; 1.0351x over previous
#include <cuda_runtime.h>
#include <cuda_bf16.h>
#include <stdint.h>

#ifndef CLAMP_VAL
#define CLAMP_VAL 10000.0f
#endif

__device__ __forceinline__ float clampv(float v) {
    return fminf(fmaxf(v, -CLAMP_VAL), CLAMP_VAL);
}

// ---------------------------------------------------------------------------
// Fast path: in_w = 8192, out_w = 8191. One block per row, TPB=512.
// Aligned 128-bit on BOTH sides; per-row 4-byte phase (lead = row & 3)
// resolved by register shuffle from two overlapping aligned input vectors.
// Loads default-cached (overlap line = L1 hit); stores evict-first.
// This is the empirically fastest structure (R4); DRAM-ceiling bound at
// ~6.7 TB/s effective (84% of spec).
// ---------------------------------------------------------------------------
constexpr int TPB = 512;

__global__ void __launch_bounds__(TPB)
binagg_row_kernel(const float4* __restrict__ x4, float* __restrict__ out)
{
    const unsigned r = blockIdx.x;
    const float4* xrow = x4 + (size_t)r * 2048u;           // 8192 floats / 4
    const float*  xs   = (const float*)xrow;
    float*        orow = out + (size_t)r * 8191u;
    const int tid  = threadIdx.x;
    const int lead = (int)(r & 3u);                         // out-row phase

    // Head: cols 0..lead-1 (0..3 scalars)
    if (tid < lead) orow[tid] = clampv(__ldg(xs + tid));

    // Aligned out-vectors covering cols [lead, lead+4*count), max col <= 8189
    const int count = ((8186 - lead) >> 2) + 1;             // 2047 or 2046
    float4* ov = (float4*)(orow + lead);                    // 16B aligned

    if (lead == 0) {
        #pragma unroll 4
        for (int v = tid; v < count; v += TPB) {
            float4 a = __ldg(&xrow[v]);
            float4 s = { clampv(a.x), clampv(a.y), clampv(a.z), clampv(a.w) };
            __stcs(&ov[v], s);
        }
    } else if (lead == 1) {
        #pragma unroll 4
        for (int v = tid; v < count; v += TPB) {
            float4 a = __ldg(&xrow[v]);
            float4 b = __ldg(&xrow[v + 1]);
            float4 s = { clampv(a.y), clampv(a.z), clampv(a.w), clampv(b.x) };
            __stcs(&ov[v], s);
        }
    } else if (lead == 2) {
        #pragma unroll 4
        for (int v = tid; v < count; v += TPB) {
            float4 a = __ldg(&xrow[v]);
            float4 b = __ldg(&xrow[v + 1]);
            float4 s = { clampv(a.z), clampv(a.w), clampv(b.x), clampv(b.y) };
            __stcs(&ov[v], s);
        }
    } else {
        #pragma unroll 4
        for (int v = tid; v < count; v += TPB) {
            float4 a = __ldg(&xrow[v]);
            float4 b = __ldg(&xrow[v + 1]);
            float4 s = { clampv(a.w), clampv(b.x), clampv(b.y), clampv(b.z) };
            __stcs(&ov[v], s);
        }
    }

    // Tail: cols [lead + 4*count, 8190]; col 8190 = mean of last two inputs
    const int tstart = lead + 4 * count;
    for (int c = tstart + tid; c <= 8190; c += TPB) {
        float val = (c == 8190)
                  ? 0.5f * (__ldg(xs + 8190) + __ldg(xs + 8191))
                  : __ldg(xs + c);
        orow[c] = clampv(val);
    }
}

// ---------------------------------------------------------------------------
// Generic fallback (any in_w/out_w): flat output indexing, scalar.
// ---------------------------------------------------------------------------
__global__ void __launch_bounds__(256)
binagg_generic_kernel(const float* __restrict__ x, float* __restrict__ out,
                      int in_w, int out_w, unsigned total)
{
    unsigned oo = blockIdx.x * blockDim.x + threadIdx.x;
    if (oo >= total) return;
    unsigned r = oo / (unsigned)out_w;
    unsigned c = oo - r * (unsigned)out_w;
    const float* xr = x + (size_t)r * (size_t)in_w;
    float val;
    if (c < (unsigned)(out_w - 1)) {
        val = __ldg(xr + c);
    } else {
        float s = 0.0f;
        for (int k = out_w - 1; k < in_w; ++k) s += __ldg(xr + k);
        val = s / (float)(in_w - out_w + 1);
    }
    out[oo] = clampv(val);
}

extern "C" void kernel_launch(void* const* d_in, const int* in_sizes, int n_in,
                              void* d_out, int out_size)
{
    const float* x = (const float*)d_in[0];
    float* out = (float*)d_out;

    const int in_w = 8192;
    int batch = in_sizes[0] / in_w;
    int out_w = (batch > 0) ? out_size / batch : 0;

    bool fast = (batch > 0) &&
                (batch * in_w == in_sizes[0]) &&
                (out_w == in_w - 1) &&
                ((size_t)batch * (size_t)out_w == (size_t)out_size);

    if (fast) {
        binagg_row_kernel<<<batch, TPB>>>((const float4*)x, out);
    } else {
        int iw = in_sizes[0];
        int ow = out_size;
        for (int cand = 8192; cand >= 1; cand >>= 1) {
            if (in_sizes[0] % cand == 0) {
                int bb = in_sizes[0] / cand;
                if (bb > 0 && out_size % bb == 0) { iw = cand; ow = out_size / bb; break; }
            }
        }
        unsigned total = (unsigned)out_size;
        unsigned blocks = (total + 255) / 256;
        binagg_generic_kernel<<<blocks, 256>>>(x, out, iw, ow, total);
    }
}